// round 14
// baseline (speedup 1.0000x reference)
#include <cuda_runtime.h>
#include <cuda_bf16.h>
#include <cstdint>

// ---------------------------------------------------------------------------
// GCNEncoder: 2-layer GCN.
//   h1 = relu( Dinv (A+I) Dinv (x @ W1) + b1 )
//   out =      Dinv (A+I) Dinv (h1 @ W2) + b2
// N = 100000, E = 1600000, CH = 128.
// R14: warp-specialized fusion of gather1 + GEMM2 (8 producer warps gather
// next tile while 8 consumer warps MMA current tile). GEMM1 persistent with
// resident W + fused x-split. CSR pull gather for final layer.
// (tcgen05 unavailable: harness compiles PTX at sm_100, no 'a'.)
// ---------------------------------------------------------------------------

#define MAX_N 100000
#define MAX_E 1600000
#define CH 128
#define PGRID 148

__device__ alignas(16) float g_h[(size_t)MAX_N * CH];    // gemm1 output (h1 pre-agg)
__device__ alignas(16) float g_h2[(size_t)MAX_N * CH];   // gemm2 output
__device__ alignas(16) __nv_bfloat16 g_W1hi[CH * CH];    // [n][k] transposed
__device__ alignas(16) __nv_bfloat16 g_W1lo[CH * CH];
__device__ alignas(16) __nv_bfloat16 g_W2hi[CH * CH];
__device__ alignas(16) __nv_bfloat16 g_W2lo[CH * CH];
__device__ float g_dinv[MAX_N];
__device__ int   g_deg[MAX_N];
__device__ int   g_row[MAX_N];
__device__ int   g_cur[MAX_N];
__device__ int   g_idx[2 * MAX_E];
__device__ int2  g_csr[MAX_E];
__device__ unsigned int g_alloc;

// ---------------------------------------------------------------------------
// (1) zero degrees + allocator.
// ---------------------------------------------------------------------------
__global__ void zero_kernel(int n) {
    int i = blockIdx.x * blockDim.x + threadIdx.x;
    if (i < n) g_deg[i] = 0;
    if (i == 0) g_alloc = 0u;
}

// ---------------------------------------------------------------------------
// (2) convert indices to int32 + in-degrees. Dtype detection inline per
// block: int64 values in [0,N) have zero high words over the first 2048
// words; int32 random values essentially never do.
// ---------------------------------------------------------------------------
__global__ void __launch_bounds__(256)
convert_kernel(const void* __restrict__ ei, int E) {
    __shared__ unsigned int s_or;
    const unsigned int* w = (const unsigned int*)ei;
    int nwords = 4 * E;                 // conservative lower bound not needed; 2E ints min
    unsigned int v = 0;
    for (int j = threadIdx.x; j < 1024; j += blockDim.x) {
        int idx = 2 * j + 1;
        if (idx < nwords) v |= w[idx];
    }
    for (int off = 16; off > 0; off >>= 1)
        v |= __shfl_down_sync(0xFFFFFFFFu, v, off);
    if (threadIdx.x == 0) s_or = 0u;
    __syncthreads();
    if ((threadIdx.x & 31) == 0 && v) atomicOr(&s_or, v);
    __syncthreads();
    bool is64 = (s_or == 0u);

    int i = blockIdx.x * blockDim.x + threadIdx.x;
    if (i >= 2 * E) return;
    int val = is64 ? (int)((const long long*)ei)[i] : ((const int*)ei)[i];
    g_idx[i] = val;
    if (i >= E) atomicAdd(&g_deg[val], 1);
}

// ---------------------------------------------------------------------------
// (3) Split W1/W2 to bf16 hi/lo as B[n][k] (block 0 = W1, block 1 = W2).
// ---------------------------------------------------------------------------
__global__ void __launch_bounds__(256)
split_w_kernel(const float* __restrict__ W1, const float* __restrict__ W2) {
    int b = blockIdx.x;
    int tid = threadIdx.x;
    const float* W = (b == 0) ? W1 : W2;
    __nv_bfloat16* dh = (b == 0) ? g_W1hi : g_W2hi;
    __nv_bfloat16* dl = (b == 0) ? g_W1lo : g_W2lo;
#pragma unroll
    for (int i = 0; i < 8; i++) {
        int chunk = tid + i * 256;
        int k = chunk >> 4;
        int n8 = (chunk & 15) * 8;
        const float4* src = (const float4*)(W + (size_t)k * CH + n8);
        float4 v0 = src[0], v1 = src[1];
        float vv[8] = {v0.x, v0.y, v0.z, v0.w, v1.x, v1.y, v1.z, v1.w};
#pragma unroll
        for (int j = 0; j < 8; j++) {
            __nv_bfloat16 h = __float2bfloat16(vv[j]);
            __nv_bfloat16 l = __float2bfloat16(vv[j] - __bfloat162float(h));
            dh[(n8 + j) * CH + k] = h;
            dl[(n8 + j) * CH + k] = l;
        }
    }
}

// ---------------------------------------------------------------------------
// (5) dinv + CSR row allocation (block scan + atomic base).
// ---------------------------------------------------------------------------
__global__ void __launch_bounds__(256)
dinv_alloc_kernel(int n) {
    int i = blockIdx.x * 256 + threadIdx.x;
    int lane = threadIdx.x & 31;
    int wid = threadIdx.x >> 5;
    int d = (i < n) ? g_deg[i] : 0;
    if (i < n) g_dinv[i] = rsqrtf((float)d + 1.0f);

    int v = d;
#pragma unroll
    for (int off = 1; off < 32; off <<= 1) {
        int t = __shfl_up_sync(0xFFFFFFFFu, v, off);
        if (lane >= off) v += t;
    }
    __shared__ int wsum[8];
    __shared__ int woff[8];
    __shared__ int base;
    if (lane == 31) wsum[wid] = v;
    __syncthreads();
    if (threadIdx.x == 0) {
        int run = 0;
#pragma unroll
        for (int w = 0; w < 8; w++) { woff[w] = run; run += wsum[w]; }
        base = (int)atomicAdd(&g_alloc, (unsigned int)run);
    }
    __syncthreads();
    if (i < n) {
        int start = base + woff[wid] + (v - d);
        g_row[i] = start;
        g_cur[i] = start;
    }
}

// (6) Fill CSR: (src, coef) per edge, grouped by dst.
__global__ void csr_fill_kernel(int E) {
    int e = blockIdx.x * blockDim.x + threadIdx.x;
    if (e >= E) return;
    int s = g_idx[e];
    int d = g_idx[E + e];
    float coef = g_dinv[s] * g_dinv[d];
    int pos = atomicAdd(&g_cur[d], 1);
    g_csr[pos] = make_int2(s, __float_as_int(coef));
}

// ---------------------------------------------------------------------------
// MMA / ldmatrix / cp.async helpers
// ---------------------------------------------------------------------------
__device__ __forceinline__ void mma_bf16(float* c, const unsigned* a, const unsigned* b) {
    asm volatile(
        "mma.sync.aligned.m16n8k16.row.col.f32.bf16.bf16.f32 "
        "{%0,%1,%2,%3}, {%4,%5,%6,%7}, {%8,%9}, {%0,%1,%2,%3};"
        : "+f"(c[0]), "+f"(c[1]), "+f"(c[2]), "+f"(c[3])
        : "r"(a[0]), "r"(a[1]), "r"(a[2]), "r"(a[3]), "r"(b[0]), "r"(b[1]));
}
__device__ __forceinline__ void ldsm_x4(unsigned* r, unsigned addr) {
    asm volatile("ldmatrix.sync.aligned.m8n8.x4.shared.b16 {%0,%1,%2,%3}, [%4];"
                 : "=r"(r[0]), "=r"(r[1]), "=r"(r[2]), "=r"(r[3]) : "r"(addr));
}
__device__ __forceinline__ void cpa16(unsigned dst, const void* src) {
    asm volatile("cp.async.cg.shared.global [%0], [%1], 16;"
                 :: "r"(dst), "l"(src) : "memory");
}
#define CP_COMMIT() asm volatile("cp.async.commit_group;" ::: "memory")
#define CP_WAIT0()  asm volatile("cp.async.wait_group 0;" ::: "memory")
__device__ __forceinline__ unsigned smem_u32g(const void* p) {
    unsigned a;
    asm("{ .reg .u64 t; cvta.to.shared.u64 t, %1; cvt.u32.u64 %0, t; }"
        : "=r"(a) : "l"(p));
    return a;
}

#define SROW_B 272                     // smem row stride bytes (136 bf16)
#define ARR_B  (128 * SROW_B)          // 34816: 128-row bf16 array
#define A64_B  (64 * SROW_B)           // 17408: 64-row bf16 array

// ---------------------------------------------------------------------------
// (4) GEMM1 (persistent): g_h = xsplit(x) @ W1^T. 148 CTAs x 512 thr,
// 16 warps as 4x4 -> 32x32/warp, M-tile 128, W resident, x reg-prefetch.
// ---------------------------------------------------------------------------
#define G1_SM_WH 0
#define G1_SM_WL ARR_B
#define G1_SM_A  (2 * ARR_B)
#define G1_SMEM  (4 * ARR_B)           // 139264

__global__ void __launch_bounds__(512)
gemm1_kernel(const float* __restrict__ X, float* __restrict__ C,
             int n, int ntiles) {
    extern __shared__ char smem[];
    const int tid = threadIdx.x;
    const int lane = tid & 31;
    const int wid = tid >> 5;
    const int wm = (wid & 3) * 32;
    const int wn = (wid >> 2) * 32;
    const int gid = lane >> 2;
    const int tig = lane & 3;
    unsigned sb = smem_u32g(smem);

    {   // W resident
#pragma unroll
        for (int i = 0; i < 4; i++) {
            int chunk = tid + i * 512;
            int r = chunk >> 4;
            int cB = (chunk & 15) * 16;
            cpa16(sb + G1_SM_WH + r * SROW_B + cB, (const char*)g_W1hi + r * 256 + cB);
            cpa16(sb + G1_SM_WL + r * SROW_B + cB, (const char*)g_W1lo + r * 256 + cB);
        }
        CP_COMMIT();
    }

    const unsigned a_off = (unsigned)((wm + (lane & 15)) * SROW_B + (lane >> 4) * 16);
    const unsigned b_off = (unsigned)((wn + (lane & 7) + ((lane >> 4) << 3)) * SROW_B
                                      + ((lane >> 3) & 1) * 16);

    float4 pf[8];
    auto load_x = [&](int tile) {
#pragma unroll
        for (int i = 0; i < 8; i++) {
            int chunk = tid + i * 512;
            int r = chunk >> 5;
            int c4 = (chunk & 31) * 4;
            int gr = tile * 128 + r;
            pf[i] = (gr < n) ? *(const float4*)(X + (size_t)gr * CH + c4)
                             : make_float4(0.f, 0.f, 0.f, 0.f);
        }
    };
    auto sts_x = [&]() {
        __nv_bfloat16* sah = (__nv_bfloat16*)(smem + G1_SM_A);
        __nv_bfloat16* sal = (__nv_bfloat16*)(smem + G1_SM_A + ARR_B);
#pragma unroll
        for (int i = 0; i < 8; i++) {
            int chunk = tid + i * 512;
            int r = chunk >> 5;
            int c4 = (chunk & 31) * 4;
            float vv[4] = {pf[i].x, pf[i].y, pf[i].z, pf[i].w};
            __nv_bfloat16 hi[4], lo[4];
#pragma unroll
            for (int j = 0; j < 4; j++) {
                hi[j] = __float2bfloat16(vv[j]);
                lo[j] = __float2bfloat16(vv[j] - __bfloat162float(hi[j]));
            }
            *(uint2*)(sah + r * 136 + c4) = *(uint2*)hi;
            *(uint2*)(sal + r * 136 + c4) = *(uint2*)lo;
        }
    };

    int t0 = blockIdx.x;
    if (t0 < ntiles) load_x(t0);
    CP_WAIT0();
    __syncthreads();
    for (int t = t0; t < ntiles; t += PGRID) {
        sts_x();
        __syncthreads();
        if (t + PGRID < ntiles) load_x(t + PGRID);

        float acc[2][4][4];
#pragma unroll
        for (int mt = 0; mt < 2; mt++)
#pragma unroll
            for (int nt = 0; nt < 4; nt++)
#pragma unroll
                for (int r = 0; r < 4; r++) acc[mt][nt][r] = 0.0f;
#pragma unroll
        for (int ks = 0; ks < 8; ks++) {
            const unsigned kB = ks * 32;
            unsigned ah[2][4], al[2][4];
#pragma unroll
            for (int mt = 0; mt < 2; mt++) {
                ldsm_x4(ah[mt], sb + G1_SM_A + a_off + mt * 16 * SROW_B + kB);
                ldsm_x4(al[mt], sb + G1_SM_A + ARR_B + a_off + mt * 16 * SROW_B + kB);
            }
#pragma unroll
            for (int p = 0; p < 2; p++) {
                unsigned bh[4], bl[4];
                ldsm_x4(bh, sb + G1_SM_WH + b_off + p * 16 * SROW_B + kB);
                ldsm_x4(bl, sb + G1_SM_WL + b_off + p * 16 * SROW_B + kB);
#pragma unroll
                for (int mt = 0; mt < 2; mt++) {
                    mma_bf16(acc[mt][2 * p],     ah[mt], bh);
                    mma_bf16(acc[mt][2 * p],     ah[mt], bl);
                    mma_bf16(acc[mt][2 * p],     al[mt], bh);
                    mma_bf16(acc[mt][2 * p + 1], ah[mt], bh + 2);
                    mma_bf16(acc[mt][2 * p + 1], ah[mt], bl + 2);
                    mma_bf16(acc[mt][2 * p + 1], al[mt], bh + 2);
                }
            }
        }
#pragma unroll
        for (int mt = 0; mt < 2; mt++)
#pragma unroll
            for (int nt = 0; nt < 4; nt++) {
                int r0 = t * 128 + wm + mt * 16 + gid;
                int cb = wn + nt * 8 + 2 * tig;
                if (r0 < n)
                    *(float2*)(C + (size_t)r0 * CH + cb) =
                        make_float2(acc[mt][nt][0], acc[mt][nt][1]);
                if (r0 + 8 < n)
                    *(float2*)(C + (size_t)(r0 + 8) * CH + cb) =
                        make_float2(acc[mt][nt][2], acc[mt][nt][3]);
            }
        __syncthreads();
    }
}

// ---------------------------------------------------------------------------
// (7) Fused gather1 + GEMM2. 148 CTAs x 512 thr, M-tile 64.
// Warps 0-7 (consumers): bf16x3 MMA on stage s. Warps 8-15 (producers):
// gather+relu+split next tile's 64 node rows into stage s^1.
// Lockstep double buffer with one __syncthreads per tile.
// ---------------------------------------------------------------------------
#define F_SM_WH 0
#define F_SM_WL ARR_B
#define F_SM_ST (2 * ARR_B)            // stage s: hi = +s*2*A64_B, lo = +A64_B
#define F_SMEM  (2 * ARR_B + 4 * A64_B)   // 139264

__global__ void __launch_bounds__(512)
fused_gather_gemm2_kernel(const float* __restrict__ h,
                          const float* __restrict__ bias,
                          float* __restrict__ C, int n, int ntiles) {
    extern __shared__ char smem[];
    const int tid = threadIdx.x;
    const int lane = tid & 31;
    const int wid = tid >> 5;
    unsigned sb = smem_u32g(smem);

    {   // W2 resident (all threads help)
#pragma unroll
        for (int i = 0; i < 4; i++) {
            int chunk = tid + i * 512;
            int r = chunk >> 4;
            int cB = (chunk & 15) * 16;
            cpa16(sb + F_SM_WH + r * SROW_B + cB, (const char*)g_W2hi + r * 256 + cB);
            cpa16(sb + F_SM_WL + r * SROW_B + cB, (const char*)g_W2lo + r * 256 + cB);
        }
        CP_COMMIT();
        CP_WAIT0();
    }

    const bool producer = wid >= 8;
    const int t0 = blockIdx.x;

    // ---- producer: gather 8 nodes (rows pw*8..+7) of tile t into stage s.
    const int pw = wid - 8;
    float4 bv = ((const float4*)bias)[lane];
    auto fill = [&](int t, int s) {
        unsigned st_hi = sb + F_SM_ST + s * 2 * A64_B;
        unsigned st_lo = st_hi + A64_B;
        for (int j = 0; j < 8; j++) {
            int r = pw * 8 + j;
            int node = t * 64 + r;
            float4 acc = make_float4(0.f, 0.f, 0.f, 0.f);
            if (node < n) {
                int start = g_row[node];
                int deg = g_deg[node];
                float di = g_dinv[node];
                float sl = di * di;
                float4 hv = ((const float4*)(h + (size_t)node * CH))[lane];
                acc.x = fmaf(hv.x, sl, bv.x);
                acc.y = fmaf(hv.y, sl, bv.y);
                acc.z = fmaf(hv.z, sl, bv.z);
                acc.w = fmaf(hv.w, sl, bv.w);
                for (int j0 = 0; j0 < deg; j0 += 32) {
                    int nn = min(32, deg - j0);
                    int2 e = make_int2(0, 0);
                    if (lane < nn) e = g_csr[start + j0 + lane];
#pragma unroll 8
                    for (int k = 0; k < nn; k++) {
                        int sidx = __shfl_sync(0xFFFFFFFFu, e.x, k);
                        float c = __int_as_float(__shfl_sync(0xFFFFFFFFu, e.y, k));
                        float4 v = ((const float4*)(h + (size_t)sidx * CH))[lane];
                        acc.x = fmaf(v.x, c, acc.x);
                        acc.y = fmaf(v.y, c, acc.y);
                        acc.z = fmaf(v.z, c, acc.z);
                        acc.w = fmaf(v.w, c, acc.w);
                    }
                }
            }
            float vv[4] = {fmaxf(acc.x, 0.f), fmaxf(acc.y, 0.f),
                           fmaxf(acc.z, 0.f), fmaxf(acc.w, 0.f)};
            __nv_bfloat16 hi[4], lo[4];
#pragma unroll
            for (int q = 0; q < 4; q++) {
                hi[q] = __float2bfloat16(vv[q]);
                lo[q] = __float2bfloat16(vv[q] - __bfloat162float(hi[q]));
            }
            unsigned ro = (unsigned)(r * SROW_B + lane * 8);
            *(uint2*)((char*)smem + (st_hi - sb) + ro) = *(uint2*)hi;
            *(uint2*)((char*)smem + (st_lo - sb) + ro) = *(uint2*)lo;
        }
    };

    // ---- consumer: 8 warps as 4x2 -> 16x64 per warp on 64-row stage.
    const int wm = (wid & 3) * 16;
    const int wn = (wid >> 2) * 64;
    const int gid = lane >> 2;
    const int tig = lane & 3;
    const unsigned a_off = (unsigned)((wm + (lane & 15)) * SROW_B + (lane >> 4) * 16);
    const unsigned b_off = (unsigned)((wn + (lane & 7) + ((lane >> 4) << 3)) * SROW_B
                                      + ((lane >> 3) & 1) * 16);
    auto consume = [&](int t, int s) {
        unsigned st = sb + F_SM_ST + s * 2 * A64_B;
        float acc[8][4];
#pragma unroll
        for (int nt = 0; nt < 8; nt++)
#pragma unroll
            for (int r = 0; r < 4; r++) acc[nt][r] = 0.0f;
#pragma unroll
        for (int ks = 0; ks < 8; ks++) {
            const unsigned kB = ks * 32;
            unsigned ah[4], al[4];
            ldsm_x4(ah, st + a_off + kB);
            ldsm_x4(al, st + A64_B + a_off + kB);
#pragma unroll
            for (int p = 0; p < 4; p++) {
                unsigned bh[4], bl[4];
                ldsm_x4(bh, sb + F_SM_WH + b_off + p * 16 * SROW_B + kB);
                ldsm_x4(bl, sb + F_SM_WL + b_off + p * 16 * SROW_B + kB);
                mma_bf16(acc[2 * p],     ah, bh);
                mma_bf16(acc[2 * p],     ah, bl);
                mma_bf16(acc[2 * p],     al, bh);
                mma_bf16(acc[2 * p + 1], ah, bh + 2);
                mma_bf16(acc[2 * p + 1], ah, bl + 2);
                mma_bf16(acc[2 * p + 1], al, bh + 2);
            }
        }
#pragma unroll
        for (int nt = 0; nt < 8; nt++) {
            int r0 = t * 64 + wm + gid;
            int cb = wn + nt * 8 + 2 * tig;
            if (r0 < n)
                *(float2*)(C + (size_t)r0 * CH + cb) = make_float2(acc[nt][0], acc[nt][1]);
            if (r0 + 8 < n)
                *(float2*)(C + (size_t)(r0 + 8) * CH + cb) = make_float2(acc[nt][2], acc[nt][3]);
        }
    };

    // ---- lockstep double-buffered pipeline
    if (producer && t0 < ntiles) fill(t0, 0);
    __syncthreads();
    int i = 0;
    for (int t = t0; t < ntiles; t += PGRID, i++) {
        if (producer) {
            if (t + PGRID < ntiles) fill(t + PGRID, (i + 1) & 1);
        } else {
            consume(t, i & 1);
        }
        __syncthreads();
    }
}

// ---------------------------------------------------------------------------
// (8) Final gather: out[i,:] = sum h2[src]*coef + h2[i]*dinv^2 + b2.
// ---------------------------------------------------------------------------
__global__ void __launch_bounds__(256)
gather_kernel(const float* __restrict__ h, const float* __restrict__ b,
              float* __restrict__ out, int n) {
    int node = (blockIdx.x * blockDim.x + threadIdx.x) >> 5;
    int lane = threadIdx.x & 31;
    if (node >= n) return;

    int start = g_row[node];
    int deg = g_deg[node];
    float di = g_dinv[node];
    float sl = di * di;

    float4 hv = ((const float4*)(h + (size_t)node * CH))[lane];
    float4 bv = ((const float4*)b)[lane];
    float4 acc;
    acc.x = fmaf(hv.x, sl, bv.x);
    acc.y = fmaf(hv.y, sl, bv.y);
    acc.z = fmaf(hv.z, sl, bv.z);
    acc.w = fmaf(hv.w, sl, bv.w);

    for (int j0 = 0; j0 < deg; j0 += 32) {
        int nn = min(32, deg - j0);
        int2 e = make_int2(0, 0);
        if (lane < nn) e = g_csr[start + j0 + lane];
#pragma unroll 8
        for (int k = 0; k < nn; k++) {
            int s = __shfl_sync(0xFFFFFFFFu, e.x, k);
            float c = __int_as_float(__shfl_sync(0xFFFFFFFFu, e.y, k));
            float4 v = ((const float4*)(h + (size_t)s * CH))[lane];
            acc.x = fmaf(v.x, c, acc.x);
            acc.y = fmaf(v.y, c, acc.y);
            acc.z = fmaf(v.z, c, acc.z);
            acc.w = fmaf(v.w, c, acc.w);
        }
    }
    ((float4*)(out + (size_t)node * CH))[lane] = acc;
}

// ---------------------------------------------------------------------------
// Launch. Slot 4 (ncu-profiled) = gemm1.
// ---------------------------------------------------------------------------
extern "C" void kernel_launch(void* const* d_in, const int* in_sizes, int n_in,
                              void* d_out, int out_size) {
    const float* x  = (const float*)d_in[0];
    const void*  ei = d_in[1];
    const float* W1 = (const float*)d_in[2];
    const float* b1 = (const float*)d_in[3];
    const float* W2 = (const float*)d_in[4];
    const float* b2 = (const float*)d_in[5];
    float*       out = (float*)d_out;

    const int N = in_sizes[0] / CH;
    const int E = in_sizes[1] / 2;
    const int nt128 = (N + 127) / 128;
    const int nt64 = (N + 63) / 64;

    float *hp = nullptr, *h2p = nullptr;
    cudaGetSymbolAddress((void**)&hp, g_h);
    cudaGetSymbolAddress((void**)&h2p, g_h2);

    cudaFuncSetAttribute(gemm1_kernel,
                         cudaFuncAttributeMaxDynamicSharedMemorySize, G1_SMEM);
    cudaFuncSetAttribute(fused_gather_gemm2_kernel,
                         cudaFuncAttributeMaxDynamicSharedMemorySize, F_SMEM);

    const int T = 256;
    const int edge_grid = (E + T - 1) / T;
    const int node_grid = (N + T - 1) / T;
    const int conv_grid = (2 * E + T - 1) / T;
    const int warp_grid = (N * 32 + T - 1) / T;

    zero_kernel<<<node_grid, T>>>(N);                                        // 1
    convert_kernel<<<conv_grid, T>>>(ei, E);                                 // 2
    split_w_kernel<<<2, T>>>(W1, W2);                                        // 3
    gemm1_kernel<<<PGRID, 512, G1_SMEM>>>(x, hp, N, nt128);                  // 4 (profiled)
    dinv_alloc_kernel<<<node_grid, T>>>(N);                                  // 5
    csr_fill_kernel<<<edge_grid, T>>>(E);                                    // 6
    fused_gather_gemm2_kernel<<<PGRID, 512, F_SMEM>>>(hp, b1, h2p, N, nt64); // 7
    gather_kernel<<<warp_grid, T>>>(h2p, b2, out, N);                        // 8
}

// round 16
// speedup vs baseline: 1.8387x; 1.8387x over previous
#include <cuda_runtime.h>
#include <cuda_bf16.h>
#include <cuda_fp16.h>
#include <cstdint>

// ---------------------------------------------------------------------------
// GCNEncoder: 2-layer GCN.
//   h1 = relu( Dinv (A+I) Dinv (x @ W1) + b1 )
//   out =      Dinv (A+I) Dinv (h1 @ W2) + b2
// N = 100000, E = 1600000, CH = 128.
// R16 (= R15 resubmit): persistent bf16x3 GEMM + fp16 message storage
// (halves gather L2 read traffic; fp32 accumulation end-to-end).
// (tcgen05 unavailable: harness compiles PTX at sm_100, no 'a'.)
// ---------------------------------------------------------------------------

#define MAX_N 100000
#define AROWS 100096                  // 782 * 128, padded
#define MAX_E 1600000
#define CH 128
#define PGRID 148                     // persistent grid (1 CTA/SM)

__device__ alignas(16) __half g_h[(size_t)MAX_N * CH];    // gemm1 out (fp16)
__device__ alignas(16) __half g_h2[(size_t)MAX_N * CH];   // gemm2 out (fp16)
__device__ alignas(16) __nv_bfloat16 g_Ahi[(size_t)AROWS * CH];
__device__ alignas(16) __nv_bfloat16 g_Alo[(size_t)AROWS * CH];
__device__ alignas(16) __nv_bfloat16 g_W1hi[CH * CH];     // [n][k] transposed
__device__ alignas(16) __nv_bfloat16 g_W1lo[CH * CH];
__device__ alignas(16) __nv_bfloat16 g_W2hi[CH * CH];
__device__ alignas(16) __nv_bfloat16 g_W2lo[CH * CH];
__device__ float g_dinv[MAX_N];
__device__ int   g_deg[MAX_N];
__device__ int   g_row[MAX_N];
__device__ int   g_cur[MAX_N];
__device__ int   g_idx[2 * MAX_E];
__device__ int2  g_csr[MAX_E];
__device__ unsigned int g_or_hi;
__device__ unsigned int g_alloc;

// ---------------------------------------------------------------------------
// (1) init + dtype detection. int64 indices in [0,N) have zero high words.
// ---------------------------------------------------------------------------
__global__ void init_detect_kernel(const unsigned int* __restrict__ w,
                                   int nwords, int n) {
    int i = blockIdx.x * blockDim.x + threadIdx.x;
    if (i < n) g_deg[i] = 0;
    if (i == 0) { g_alloc = 0u; }
    if (blockIdx.x == 0) {
        unsigned int v = 0;
        for (int j = threadIdx.x; j < 1024; j += blockDim.x) {
            int idx = 2 * j + 1;
            if (idx < nwords) v |= w[idx];
        }
        for (int off = 16; off > 0; off >>= 1)
            v |= __shfl_down_sync(0xFFFFFFFFu, v, off);
        __shared__ unsigned int sv[8];
        if ((threadIdx.x & 31) == 0) sv[threadIdx.x >> 5] = v;
        __syncthreads();
        if (threadIdx.x == 0) {
            unsigned int r = 0;
            for (int wz = 0; wz < (int)(blockDim.x >> 5); wz++) r |= sv[wz];
            g_or_hi = r;
        }
    }
}

// (2) convert indices to int32 + count in-degrees (dst half).
__global__ void convert_kernel(const void* __restrict__ ei, int E) {
    int i = blockIdx.x * blockDim.x + threadIdx.x;
    if (i >= 2 * E) return;
    int v;
    if (g_or_hi == 0u) v = (int)((const long long*)ei)[i];
    else               v = ((const int*)ei)[i];
    g_idx[i] = v;
    if (i >= E) atomicAdd(&g_deg[v], 1);
}

// ---------------------------------------------------------------------------
// (3) Split W1/W2 to bf16 hi/lo as B[n][k] (block 0 = W1, block 1 = W2).
// ---------------------------------------------------------------------------
__global__ void __launch_bounds__(256)
split_w_kernel(const float* __restrict__ W1, const float* __restrict__ W2) {
    int b = blockIdx.x;
    int tid = threadIdx.x;
    const float* W = (b == 0) ? W1 : W2;
    __nv_bfloat16* dh = (b == 0) ? g_W1hi : g_W2hi;
    __nv_bfloat16* dl = (b == 0) ? g_W1lo : g_W2lo;
#pragma unroll
    for (int i = 0; i < 8; i++) {
        int chunk = tid + i * 256;
        int k = chunk >> 4;
        int n8 = (chunk & 15) * 8;
        const float4* src = (const float4*)(W + (size_t)k * CH + n8);
        float4 v0 = src[0], v1 = src[1];
        float vv[8] = {v0.x, v0.y, v0.z, v0.w, v1.x, v1.y, v1.z, v1.w};
#pragma unroll
        for (int j = 0; j < 8; j++) {
            __nv_bfloat16 h = __float2bfloat16(vv[j]);
            __nv_bfloat16 l = __float2bfloat16(vv[j] - __bfloat162float(h));
            dh[(n8 + j) * CH + k] = h;
            dl[(n8 + j) * CH + k] = l;
        }
    }
}

// ---------------------------------------------------------------------------
// (5) dinv + CSR row allocation (block scan + atomic base).
// ---------------------------------------------------------------------------
__global__ void __launch_bounds__(256)
dinv_alloc_kernel(int n) {
    int i = blockIdx.x * 256 + threadIdx.x;
    int lane = threadIdx.x & 31;
    int wid = threadIdx.x >> 5;
    int d = (i < n) ? g_deg[i] : 0;
    if (i < n) g_dinv[i] = rsqrtf((float)d + 1.0f);

    int v = d;
#pragma unroll
    for (int off = 1; off < 32; off <<= 1) {
        int t = __shfl_up_sync(0xFFFFFFFFu, v, off);
        if (lane >= off) v += t;
    }
    __shared__ int wsum[8];
    __shared__ int woff[8];
    __shared__ int base;
    if (lane == 31) wsum[wid] = v;
    __syncthreads();
    if (threadIdx.x == 0) {
        int run = 0;
#pragma unroll
        for (int w = 0; w < 8; w++) { woff[w] = run; run += wsum[w]; }
        base = (int)atomicAdd(&g_alloc, (unsigned int)run);
    }
    __syncthreads();
    if (i < n) {
        int start = base + woff[wid] + (v - d);
        g_row[i] = start;
        g_cur[i] = start;
    }
}

// (6) Fill CSR: (src, coef) per edge, grouped by dst.
__global__ void csr_fill_kernel(int E) {
    int e = blockIdx.x * blockDim.x + threadIdx.x;
    if (e >= E) return;
    int s = g_idx[e];
    int d = g_idx[E + e];
    float coef = g_dinv[s] * g_dinv[d];
    int pos = atomicAdd(&g_cur[d], 1);
    g_csr[pos] = make_int2(s, __float_as_int(coef));
}

// ---------------------------------------------------------------------------
// (4,8) Persistent GEMM: C(fp16) = A @ B^T, bf16x3, m16n8k16 + ldmatrix.
// 148 CTAs x 512 threads (16 warps as 4x4 -> 32x32/warp), M-tile 128.
// W hi/lo resident in smem for all tiles.
// LAYER 1: A = fp32 x rows, split in-kernel, next tile prefetched to regs.
// LAYER 2: A hi/lo cp.async double-buffered from row-major images.
// ---------------------------------------------------------------------------
__device__ __forceinline__ void mma_bf16(float* c, const unsigned* a, const unsigned* b) {
    asm volatile(
        "mma.sync.aligned.m16n8k16.row.col.f32.bf16.bf16.f32 "
        "{%0,%1,%2,%3}, {%4,%5,%6,%7}, {%8,%9}, {%0,%1,%2,%3};"
        : "+f"(c[0]), "+f"(c[1]), "+f"(c[2]), "+f"(c[3])
        : "r"(a[0]), "r"(a[1]), "r"(a[2]), "r"(a[3]), "r"(b[0]), "r"(b[1]));
}
__device__ __forceinline__ void ldsm_x4(unsigned* r, unsigned addr) {
    asm volatile("ldmatrix.sync.aligned.m8n8.x4.shared.b16 {%0,%1,%2,%3}, [%4];"
                 : "=r"(r[0]), "=r"(r[1]), "=r"(r[2]), "=r"(r[3]) : "r"(addr));
}
__device__ __forceinline__ void cpa16(unsigned dst, const void* src) {
    asm volatile("cp.async.cg.shared.global [%0], [%1], 16;"
                 :: "r"(dst), "l"(src) : "memory");
}
#define CP_COMMIT() asm volatile("cp.async.commit_group;" ::: "memory")
#define CP_WAIT0()  asm volatile("cp.async.wait_group 0;" ::: "memory")

#define SROW_B 272                     // smem row stride bytes (136 bf16)
#define ARR_B  (128 * SROW_B)          // 34816 B: one 128-row bf16 array
#define SM_WH  0
#define SM_WL  ARR_B
#define SM_A0  (2 * ARR_B)
#define SMEM_L1 (4 * ARR_B)            // 139264
#define SMEM_L2 (6 * ARR_B)            // 208896

template <int LAYER>
__global__ void __launch_bounds__(512)
gemm_bf16_kernel(const float* __restrict__ X, __half* __restrict__ C,
                 int n, int ntiles) {
    extern __shared__ char smem[];
    const int tid = threadIdx.x;
    const int lane = tid & 31;
    const int wid = tid >> 5;
    const int wm = (wid & 3) * 32;
    const int wn = (wid >> 2) * 32;
    const int gid = lane >> 2;
    const int tig = lane & 3;

    unsigned sb;
    asm("{ .reg .u64 t; cvta.to.shared.u64 t, %1; cvt.u32.u64 %0, t; }"
        : "=r"(sb) : "l"(smem));

    {   // W resident
        const char* wh = (const char*)(LAYER == 1 ? g_W1hi : g_W2hi);
        const char* wl = (const char*)(LAYER == 1 ? g_W1lo : g_W2lo);
#pragma unroll
        for (int i = 0; i < 4; i++) {
            int chunk = tid + i * 512;
            int r = chunk >> 4;
            int cB = (chunk & 15) * 16;
            cpa16(sb + SM_WH + r * SROW_B + cB, wh + r * 256 + cB);
            cpa16(sb + SM_WL + r * SROW_B + cB, wl + r * 256 + cB);
        }
        CP_COMMIT();
    }

    const unsigned a_off = (unsigned)((wm + (lane & 15)) * SROW_B + (lane >> 4) * 16);
    const unsigned b_off = (unsigned)((wn + (lane & 7) + ((lane >> 4) << 3)) * SROW_B
                                      + ((lane >> 3) & 1) * 16);

    float4 pf[8];
    auto load_x = [&](int tile) {
#pragma unroll
        for (int i = 0; i < 8; i++) {
            int chunk = tid + i * 512;
            int r = chunk >> 5;
            int c4 = (chunk & 31) * 4;
            int gr = tile * 128 + r;
            pf[i] = (gr < n) ? *(const float4*)(X + (size_t)gr * CH + c4)
                             : make_float4(0.f, 0.f, 0.f, 0.f);
        }
    };
    auto sts_x = [&](unsigned stage) {
        __nv_bfloat16* sah = (__nv_bfloat16*)(smem + stage);
        __nv_bfloat16* sal = (__nv_bfloat16*)(smem + stage + ARR_B);
#pragma unroll
        for (int i = 0; i < 8; i++) {
            int chunk = tid + i * 512;
            int r = chunk >> 5;
            int c4 = (chunk & 31) * 4;
            float vv[4] = {pf[i].x, pf[i].y, pf[i].z, pf[i].w};
            __nv_bfloat16 hi[4], lo[4];
#pragma unroll
            for (int j = 0; j < 4; j++) {
                hi[j] = __float2bfloat16(vv[j]);
                lo[j] = __float2bfloat16(vv[j] - __bfloat162float(hi[j]));
            }
            *(uint2*)(sah + r * 136 + c4) = *(uint2*)hi;
            *(uint2*)(sal + r * 136 + c4) = *(uint2*)lo;
        }
    };
    auto issue_a = [&](int tile, unsigned stage) {
#pragma unroll
        for (int i = 0; i < 4; i++) {
            int chunk = tid + i * 512;
            int r = chunk >> 4;
            int cB = (chunk & 15) * 16;
            size_t g = (size_t)(tile * 128 + r) * 256 + cB;   // rows < AROWS
            cpa16(sb + stage + r * SROW_B + cB, (const char*)g_Ahi + g);
            cpa16(sb + stage + ARR_B + r * SROW_B + cB, (const char*)g_Alo + g);
        }
        CP_COMMIT();
    };

    auto compute_store = [&](unsigned stage, int tile) {
        float acc[2][4][4];
#pragma unroll
        for (int mt = 0; mt < 2; mt++)
#pragma unroll
            for (int nt = 0; nt < 4; nt++)
#pragma unroll
                for (int r = 0; r < 4; r++) acc[mt][nt][r] = 0.0f;

#pragma unroll
        for (int ks = 0; ks < 8; ks++) {
            const unsigned kB = ks * 32;
            unsigned ah[2][4], al[2][4];
#pragma unroll
            for (int mt = 0; mt < 2; mt++) {
                ldsm_x4(ah[mt], sb + stage + a_off + mt * 16 * SROW_B + kB);
                ldsm_x4(al[mt], sb + stage + ARR_B + a_off + mt * 16 * SROW_B + kB);
            }
#pragma unroll
            for (int p = 0; p < 2; p++) {
                unsigned bh[4], bl[4];
                ldsm_x4(bh, sb + SM_WH + b_off + p * 16 * SROW_B + kB);
                ldsm_x4(bl, sb + SM_WL + b_off + p * 16 * SROW_B + kB);
#pragma unroll
                for (int mt = 0; mt < 2; mt++) {
                    mma_bf16(acc[mt][2 * p],     ah[mt], bh);
                    mma_bf16(acc[mt][2 * p],     ah[mt], bl);
                    mma_bf16(acc[mt][2 * p],     al[mt], bh);
                    mma_bf16(acc[mt][2 * p + 1], ah[mt], bh + 2);
                    mma_bf16(acc[mt][2 * p + 1], ah[mt], bl + 2);
                    mma_bf16(acc[mt][2 * p + 1], al[mt], bh + 2);
                }
            }
        }
        // fp16 epilogue: half2 per (row, col-pair)
#pragma unroll
        for (int mt = 0; mt < 2; mt++)
#pragma unroll
            for (int nt = 0; nt < 4; nt++) {
                int r0 = tile * 128 + wm + mt * 16 + gid;
                int cb = wn + nt * 8 + 2 * tig;
                if (r0 < n)
                    *(__half2*)(C + (size_t)r0 * CH + cb) =
                        __floats2half2_rn(acc[mt][nt][0], acc[mt][nt][1]);
                if (r0 + 8 < n)
                    *(__half2*)(C + (size_t)(r0 + 8) * CH + cb) =
                        __floats2half2_rn(acc[mt][nt][2], acc[mt][nt][3]);
            }
    };

    if (LAYER == 1) {
        int t0 = blockIdx.x;
        if (t0 < ntiles) load_x(t0);
        CP_WAIT0();
        __syncthreads();
        for (int t = t0; t < ntiles; t += PGRID) {
            sts_x(SM_A0);
            __syncthreads();
            if (t + PGRID < ntiles) load_x(t + PGRID);
            compute_store(SM_A0, t);
            __syncthreads();
        }
    } else {
        int t0 = blockIdx.x;
        if (t0 < ntiles) issue_a(t0, SM_A0);
        int s = 0;
        for (int t = t0; t < ntiles; t += PGRID) {
            CP_WAIT0();
            __syncthreads();
            if (t + PGRID < ntiles)
                issue_a(t + PGRID, SM_A0 + (s ^ 1) * 2 * ARR_B);
            compute_store(SM_A0 + s * 2 * ARR_B, t);
            s ^= 1;
        }
    }
}

// ---------------------------------------------------------------------------
// (7,9) Pull aggregation over fp16 h: one warp per node, fp32 accumulation.
// Each lane owns 4 channels (uint2 = 4 halves per row read, 256B/row/warp).
// SPLIT=true: relu + write bf16 hi/lo rows (feeds GEMM2).
// SPLIT=false: write fp32 rows (final output).
// ---------------------------------------------------------------------------
template <bool SPLIT>
__global__ void __launch_bounds__(256)
gather_kernel(const __half* __restrict__ h, const float* __restrict__ b,
              float* __restrict__ out, int n) {
    int node = (blockIdx.x * blockDim.x + threadIdx.x) >> 5;
    int lane = threadIdx.x & 31;
    if (node >= n) return;

    int start = g_row[node];
    int deg = g_deg[node];
    float di = g_dinv[node];
    float sl = di * di;

    uint2 su = ((const uint2*)(h + (size_t)node * CH))[lane];
    float2 s0 = __half22float2(*(__half2*)&su.x);
    float2 s1 = __half22float2(*(__half2*)&su.y);
    float4 bv = ((const float4*)b)[lane];
    float4 acc;
    acc.x = fmaf(s0.x, sl, bv.x);
    acc.y = fmaf(s0.y, sl, bv.y);
    acc.z = fmaf(s1.x, sl, bv.z);
    acc.w = fmaf(s1.y, sl, bv.w);

    for (int j0 = 0; j0 < deg; j0 += 32) {
        int nn = min(32, deg - j0);
        int2 e = make_int2(0, 0);
        if (lane < nn) e = g_csr[start + j0 + lane];
#pragma unroll 8
        for (int k = 0; k < nn; k++) {
            int s = __shfl_sync(0xFFFFFFFFu, e.x, k);
            float c = __int_as_float(__shfl_sync(0xFFFFFFFFu, e.y, k));
            uint2 u = ((const uint2*)(h + (size_t)s * CH))[lane];
            float2 f0 = __half22float2(*(__half2*)&u.x);
            float2 f1 = __half22float2(*(__half2*)&u.y);
            acc.x = fmaf(f0.x, c, acc.x);
            acc.y = fmaf(f0.y, c, acc.y);
            acc.z = fmaf(f1.x, c, acc.z);
            acc.w = fmaf(f1.y, c, acc.w);
        }
    }

    if (SPLIT) {
        float vv[4] = {fmaxf(acc.x, 0.f), fmaxf(acc.y, 0.f),
                       fmaxf(acc.z, 0.f), fmaxf(acc.w, 0.f)};
        __nv_bfloat16 hi[4], lo[4];
#pragma unroll
        for (int j = 0; j < 4; j++) {
            hi[j] = __float2bfloat16(vv[j]);
            lo[j] = __float2bfloat16(vv[j] - __bfloat162float(hi[j]));
        }
        size_t off = (size_t)node * CH + lane * 4;
        *(uint2*)(g_Ahi + off) = *(uint2*)hi;
        *(uint2*)(g_Alo + off) = *(uint2*)lo;
    } else {
        ((float4*)(out + (size_t)node * CH))[lane] = acc;
    }
}

// ---------------------------------------------------------------------------
// Launch. Slot 4 (ncu-profiled) = gemm layer 1.
// ---------------------------------------------------------------------------
extern "C" void kernel_launch(void* const* d_in, const int* in_sizes, int n_in,
                              void* d_out, int out_size) {
    const float* x  = (const float*)d_in[0];
    const void*  ei = d_in[1];
    const float* W1 = (const float*)d_in[2];
    const float* b1 = (const float*)d_in[3];
    const float* W2 = (const float*)d_in[4];
    const float* b2 = (const float*)d_in[5];
    float*       out = (float*)d_out;

    const int N = in_sizes[0] / CH;
    const int E = in_sizes[1] / 2;
    const int ntiles = (N + 127) / 128;

    __half *hp = nullptr, *h2p = nullptr;
    cudaGetSymbolAddress((void**)&hp, g_h);
    cudaGetSymbolAddress((void**)&h2p, g_h2);

    cudaFuncSetAttribute(gemm_bf16_kernel<1>,
                         cudaFuncAttributeMaxDynamicSharedMemorySize, SMEM_L1);
    cudaFuncSetAttribute(gemm_bf16_kernel<2>,
                         cudaFuncAttributeMaxDynamicSharedMemorySize, SMEM_L2);

    const int T = 256;
    const int edge_grid = (E + T - 1) / T;
    const int node_grid = (N + T - 1) / T;
    const int conv_grid = (2 * E + T - 1) / T;
    const int warp_grid = (N * 32 + T - 1) / T;

    init_detect_kernel<<<node_grid, T>>>((const unsigned int*)ei, 2 * E, N); // 1
    convert_kernel<<<conv_grid, T>>>(ei, E);                                 // 2
    split_w_kernel<<<2, T>>>(W1, W2);                                        // 3
    gemm_bf16_kernel<1><<<PGRID, 512, SMEM_L1>>>(x, hp, N, ntiles);          // 4 (profiled)
    dinv_alloc_kernel<<<node_grid, T>>>(N);                                  // 5
    csr_fill_kernel<<<edge_grid, T>>>(E);                                    // 6
    gather_kernel<true><<<warp_grid, T>>>(hp, b1, nullptr, N);               // 7
    gemm_bf16_kernel<2><<<PGRID, 512, SMEM_L2>>>(nullptr, h2p, N, ntiles);   // 8
    gather_kernel<false><<<warp_grid, T>>>(h2p, b2, out, N);                 // 9
}

// round 17
// speedup vs baseline: 2.0538x; 1.1170x over previous
#include <cuda_runtime.h>
#include <cuda_bf16.h>
#include <cuda_fp16.h>
#include <cstdint>

// ---------------------------------------------------------------------------
// GCNEncoder: 2-layer GCN.
//   h1 = relu( Dinv (A+I) Dinv (x @ W1) + b1 )
//   out =      Dinv (A+I) Dinv (h1 @ W2) + b2
// N = 100000, E = 1600000, CH = 128.
// R17: 2-term fp16 GEMM: C = fp16(A) @ (Whi + Wlo)^T with fp16 hi/lo W split
// (W near-exact; only error = A rounded to fp16 — same class as the fp16
// message storage validated in R16). A is a single fp16 array; the bf16
// hi/lo images and their split passes are gone. fp16 messages for gathers.
// (tcgen05 unavailable: harness compiles PTX at sm_100, no 'a'.)
// ---------------------------------------------------------------------------

#define MAX_N 100000
#define AROWS 100096                  // 782 * 128, padded
#define MAX_E 1600000
#define CH 128
#define PGRID 148                     // persistent grid (1 CTA/SM)

__device__ alignas(16) __half g_h[(size_t)MAX_N * CH];    // gemm1 out (fp16)
__device__ alignas(16) __half g_h2[(size_t)MAX_N * CH];   // gemm2 out (fp16)
__device__ alignas(16) __half g_a2[(size_t)AROWS * CH];   // gather1 out = gemm2 A
__device__ alignas(16) __half g_W1hi[CH * CH];            // [n][k] transposed
__device__ alignas(16) __half g_W1lo[CH * CH];
__device__ alignas(16) __half g_W2hi[CH * CH];
__device__ alignas(16) __half g_W2lo[CH * CH];
__device__ float g_dinv[MAX_N];
__device__ int   g_deg[MAX_N];
__device__ int   g_row[MAX_N];
__device__ int   g_cur[MAX_N];
__device__ int   g_idx[2 * MAX_E];
__device__ int2  g_csr[MAX_E];
__device__ unsigned int g_or_hi;
__device__ unsigned int g_alloc;

// ---------------------------------------------------------------------------
// (1) init + dtype detection. int64 indices in [0,N) have zero high words.
// ---------------------------------------------------------------------------
__global__ void init_detect_kernel(const unsigned int* __restrict__ w,
                                   int nwords, int n) {
    int i = blockIdx.x * blockDim.x + threadIdx.x;
    if (i < n) g_deg[i] = 0;
    if (i == 0) { g_alloc = 0u; }
    if (blockIdx.x == 0) {
        unsigned int v = 0;
        for (int j = threadIdx.x; j < 1024; j += blockDim.x) {
            int idx = 2 * j + 1;
            if (idx < nwords) v |= w[idx];
        }
        for (int off = 16; off > 0; off >>= 1)
            v |= __shfl_down_sync(0xFFFFFFFFu, v, off);
        __shared__ unsigned int sv[8];
        if ((threadIdx.x & 31) == 0) sv[threadIdx.x >> 5] = v;
        __syncthreads();
        if (threadIdx.x == 0) {
            unsigned int r = 0;
            for (int wz = 0; wz < (int)(blockDim.x >> 5); wz++) r |= sv[wz];
            g_or_hi = r;
        }
    }
}

// (2) convert indices to int32 + count in-degrees (dst half).
__global__ void convert_kernel(const void* __restrict__ ei, int E) {
    int i = blockIdx.x * blockDim.x + threadIdx.x;
    if (i >= 2 * E) return;
    int v;
    if (g_or_hi == 0u) v = (int)((const long long*)ei)[i];
    else               v = ((const int*)ei)[i];
    g_idx[i] = v;
    if (i >= E) atomicAdd(&g_deg[v], 1);
}

// ---------------------------------------------------------------------------
// (3) Split W1/W2 to fp16 hi/lo as B[n][k] (block 0 = W1, block 1 = W2).
// hi = fp16(w), lo = fp16(w - hi): W represented to ~2^-22 relative.
// ---------------------------------------------------------------------------
__global__ void __launch_bounds__(256)
split_w_kernel(const float* __restrict__ W1, const float* __restrict__ W2) {
    int b = blockIdx.x;
    int tid = threadIdx.x;
    const float* W = (b == 0) ? W1 : W2;
    __half* dh = (b == 0) ? g_W1hi : g_W2hi;
    __half* dl = (b == 0) ? g_W1lo : g_W2lo;
#pragma unroll
    for (int i = 0; i < 8; i++) {
        int chunk = tid + i * 256;
        int k = chunk >> 4;
        int n8 = (chunk & 15) * 8;
        const float4* src = (const float4*)(W + (size_t)k * CH + n8);
        float4 v0 = src[0], v1 = src[1];
        float vv[8] = {v0.x, v0.y, v0.z, v0.w, v1.x, v1.y, v1.z, v1.w};
#pragma unroll
        for (int j = 0; j < 8; j++) {
            __half h = __float2half_rn(vv[j]);
            __half l = __float2half_rn(vv[j] - __half2float(h));
            dh[(n8 + j) * CH + k] = h;
            dl[(n8 + j) * CH + k] = l;
        }
    }
}

// ---------------------------------------------------------------------------
// (5) dinv + CSR row allocation (block scan + atomic base).
// ---------------------------------------------------------------------------
__global__ void __launch_bounds__(256)
dinv_alloc_kernel(int n) {
    int i = blockIdx.x * 256 + threadIdx.x;
    int lane = threadIdx.x & 31;
    int wid = threadIdx.x >> 5;
    int d = (i < n) ? g_deg[i] : 0;
    if (i < n) g_dinv[i] = rsqrtf((float)d + 1.0f);

    int v = d;
#pragma unroll
    for (int off = 1; off < 32; off <<= 1) {
        int t = __shfl_up_sync(0xFFFFFFFFu, v, off);
        if (lane >= off) v += t;
    }
    __shared__ int wsum[8];
    __shared__ int woff[8];
    __shared__ int base;
    if (lane == 31) wsum[wid] = v;
    __syncthreads();
    if (threadIdx.x == 0) {
        int run = 0;
#pragma unroll
        for (int w = 0; w < 8; w++) { woff[w] = run; run += wsum[w]; }
        base = (int)atomicAdd(&g_alloc, (unsigned int)run);
    }
    __syncthreads();
    if (i < n) {
        int start = base + woff[wid] + (v - d);
        g_row[i] = start;
        g_cur[i] = start;
    }
}

// (6) Fill CSR: (src, coef) per edge, grouped by dst.
__global__ void csr_fill_kernel(int E) {
    int e = blockIdx.x * blockDim.x + threadIdx.x;
    if (e >= E) return;
    int s = g_idx[e];
    int d = g_idx[E + e];
    float coef = g_dinv[s] * g_dinv[d];
    int pos = atomicAdd(&g_cur[d], 1);
    g_csr[pos] = make_int2(s, __float_as_int(coef));
}

// ---------------------------------------------------------------------------
// (4,8) Persistent GEMM: C(fp16) = A(fp16) @ (Whi+Wlo)^T, m16n8k16 fp16 mma,
// ldmatrix. 148 CTAs x 512 threads (16 warps as 4x4 -> 32x32/warp), M-tile
// 128. W hi/lo resident in smem; A is ONE fp16 array.
// LAYER 1: A = fp32 x rows, fp16-converted in-kernel, reg prefetch.
// LAYER 2: A = g_a2 rows (already fp16), cp.async double-buffered.
// ---------------------------------------------------------------------------
__device__ __forceinline__ void mma_f16(float* c, const unsigned* a, const unsigned* b) {
    asm volatile(
        "mma.sync.aligned.m16n8k16.row.col.f32.f16.f16.f32 "
        "{%0,%1,%2,%3}, {%4,%5,%6,%7}, {%8,%9}, {%0,%1,%2,%3};"
        : "+f"(c[0]), "+f"(c[1]), "+f"(c[2]), "+f"(c[3])
        : "r"(a[0]), "r"(a[1]), "r"(a[2]), "r"(a[3]), "r"(b[0]), "r"(b[1]));
}
__device__ __forceinline__ void ldsm_x4(unsigned* r, unsigned addr) {
    asm volatile("ldmatrix.sync.aligned.m8n8.x4.shared.b16 {%0,%1,%2,%3}, [%4];"
                 : "=r"(r[0]), "=r"(r[1]), "=r"(r[2]), "=r"(r[3]) : "r"(addr));
}
__device__ __forceinline__ void cpa16(unsigned dst, const void* src) {
    asm volatile("cp.async.cg.shared.global [%0], [%1], 16;"
                 :: "r"(dst), "l"(src) : "memory");
}
#define CP_COMMIT() asm volatile("cp.async.commit_group;" ::: "memory")
#define CP_WAIT0()  asm volatile("cp.async.wait_group 0;" ::: "memory")

#define SROW_B 272                     // smem row stride bytes (136 halves)
#define ARR_B  (128 * SROW_B)          // 34816 B: one 128-row fp16 array
#define SM_WH  0
#define SM_WL  ARR_B
#define SM_A0  (2 * ARR_B)
#define SMEM_L1 (3 * ARR_B)            // W(2) + A(1)          = 104448
#define SMEM_L2 (4 * ARR_B)            // W(2) + A stages(2)   = 139264

template <int LAYER>
__global__ void __launch_bounds__(512)
gemm_f16_kernel(const float* __restrict__ X, __half* __restrict__ C,
                int n, int ntiles) {
    extern __shared__ char smem[];
    const int tid = threadIdx.x;
    const int lane = tid & 31;
    const int wid = tid >> 5;
    const int wm = (wid & 3) * 32;
    const int wn = (wid >> 2) * 32;
    const int gid = lane >> 2;
    const int tig = lane & 3;

    unsigned sb;
    asm("{ .reg .u64 t; cvta.to.shared.u64 t, %1; cvt.u32.u64 %0, t; }"
        : "=r"(sb) : "l"(smem));

    {   // W hi/lo resident
        const char* wh = (const char*)(LAYER == 1 ? g_W1hi : g_W2hi);
        const char* wl = (const char*)(LAYER == 1 ? g_W1lo : g_W2lo);
#pragma unroll
        for (int i = 0; i < 4; i++) {
            int chunk = tid + i * 512;
            int r = chunk >> 4;
            int cB = (chunk & 15) * 16;
            cpa16(sb + SM_WH + r * SROW_B + cB, wh + r * 256 + cB);
            cpa16(sb + SM_WL + r * SROW_B + cB, wl + r * 256 + cB);
        }
        CP_COMMIT();
    }

    const unsigned a_off = (unsigned)((wm + (lane & 15)) * SROW_B + (lane >> 4) * 16);
    const unsigned b_off = (unsigned)((wn + (lane & 7) + ((lane >> 4) << 3)) * SROW_B
                                      + ((lane >> 3) & 1) * 16);

    float4 pf[8];
    auto load_x = [&](int tile) {
#pragma unroll
        for (int i = 0; i < 8; i++) {
            int chunk = tid + i * 512;
            int r = chunk >> 5;
            int c4 = (chunk & 31) * 4;
            int gr = tile * 128 + r;
            pf[i] = (gr < n) ? *(const float4*)(X + (size_t)gr * CH + c4)
                             : make_float4(0.f, 0.f, 0.f, 0.f);
        }
    };
    auto sts_x = [&](unsigned stage) {
        __half* sa = (__half*)(smem + stage);
#pragma unroll
        for (int i = 0; i < 8; i++) {
            int chunk = tid + i * 512;
            int r = chunk >> 5;
            int c4 = (chunk & 31) * 4;
            __half h[4] = {__float2half_rn(pf[i].x), __float2half_rn(pf[i].y),
                           __float2half_rn(pf[i].z), __float2half_rn(pf[i].w)};
            *(uint2*)(sa + r * 136 + c4) = *(uint2*)h;
        }
    };
    auto issue_a = [&](int tile, unsigned stage) {   // 4 chunks/thread
#pragma unroll
        for (int i = 0; i < 4; i++) {
            int chunk = tid + i * 512;      // 0..2047
            int r = chunk >> 4;
            int cB = (chunk & 15) * 16;
            size_t g = (size_t)(tile * 128 + r) * 256 + cB;   // rows < AROWS
            cpa16(sb + stage + r * SROW_B + cB, (const char*)g_a2 + g);
        }
        CP_COMMIT();
    };

    auto compute_store = [&](unsigned stage, int tile) {
        float acc[2][4][4];
#pragma unroll
        for (int mt = 0; mt < 2; mt++)
#pragma unroll
            for (int nt = 0; nt < 4; nt++)
#pragma unroll
                for (int r = 0; r < 4; r++) acc[mt][nt][r] = 0.0f;

#pragma unroll
        for (int ks = 0; ks < 8; ks++) {
            const unsigned kB = ks * 32;
            unsigned a[2][4];
#pragma unroll
            for (int mt = 0; mt < 2; mt++)
                ldsm_x4(a[mt], sb + stage + a_off + mt * 16 * SROW_B + kB);
#pragma unroll
            for (int p = 0; p < 2; p++) {
                unsigned bh[4], bl[4];
                ldsm_x4(bh, sb + SM_WH + b_off + p * 16 * SROW_B + kB);
                ldsm_x4(bl, sb + SM_WL + b_off + p * 16 * SROW_B + kB);
#pragma unroll
                for (int mt = 0; mt < 2; mt++) {
                    mma_f16(acc[mt][2 * p],     a[mt], bh);
                    mma_f16(acc[mt][2 * p],     a[mt], bl);
                    mma_f16(acc[mt][2 * p + 1], a[mt], bh + 2);
                    mma_f16(acc[mt][2 * p + 1], a[mt], bl + 2);
                }
            }
        }
        // fp16 epilogue: half2 per (row, col-pair)
#pragma unroll
        for (int mt = 0; mt < 2; mt++)
#pragma unroll
            for (int nt = 0; nt < 4; nt++) {
                int r0 = tile * 128 + wm + mt * 16 + gid;
                int cb = wn + nt * 8 + 2 * tig;
                if (r0 < n)
                    *(__half2*)(C + (size_t)r0 * CH + cb) =
                        __floats2half2_rn(acc[mt][nt][0], acc[mt][nt][1]);
                if (r0 + 8 < n)
                    *(__half2*)(C + (size_t)(r0 + 8) * CH + cb) =
                        __floats2half2_rn(acc[mt][nt][2], acc[mt][nt][3]);
            }
    };

    if (LAYER == 1) {
        int t0 = blockIdx.x;
        if (t0 < ntiles) load_x(t0);
        CP_WAIT0();
        __syncthreads();
        for (int t = t0; t < ntiles; t += PGRID) {
            sts_x(SM_A0);
            __syncthreads();
            if (t + PGRID < ntiles) load_x(t + PGRID);
            compute_store(SM_A0, t);
            __syncthreads();
        }
    } else {
        int t0 = blockIdx.x;
        if (t0 < ntiles) issue_a(t0, SM_A0);
        int s = 0;
        for (int t = t0; t < ntiles; t += PGRID) {
            CP_WAIT0();
            __syncthreads();
            if (t + PGRID < ntiles)
                issue_a(t + PGRID, SM_A0 + (s ^ 1) * ARR_B);
            compute_store(SM_A0 + s * ARR_B, t);
            s ^= 1;
        }
    }
}

// ---------------------------------------------------------------------------
// (7,9) Pull aggregation over fp16 h: one warp per node, fp32 accumulation.
// SPLIT=true: relu + write fp16 row to g_a2 (feeds GEMM2 directly).
// SPLIT=false: write fp32 rows (final output).
// ---------------------------------------------------------------------------
template <bool SPLIT>
__global__ void __launch_bounds__(256)
gather_kernel(const __half* __restrict__ h, const float* __restrict__ b,
              float* __restrict__ out, int n) {
    int node = (blockIdx.x * blockDim.x + threadIdx.x) >> 5;
    int lane = threadIdx.x & 31;
    if (node >= n) return;

    int start = g_row[node];
    int deg = g_deg[node];
    float di = g_dinv[node];
    float sl = di * di;

    uint2 su = ((const uint2*)(h + (size_t)node * CH))[lane];
    float2 s0 = __half22float2(*(__half2*)&su.x);
    float2 s1 = __half22float2(*(__half2*)&su.y);
    float4 bv = ((const float4*)b)[lane];
    float4 acc;
    acc.x = fmaf(s0.x, sl, bv.x);
    acc.y = fmaf(s0.y, sl, bv.y);
    acc.z = fmaf(s1.x, sl, bv.z);
    acc.w = fmaf(s1.y, sl, bv.w);

    for (int j0 = 0; j0 < deg; j0 += 32) {
        int nn = min(32, deg - j0);
        int2 e = make_int2(0, 0);
        if (lane < nn) e = g_csr[start + j0 + lane];
#pragma unroll 8
        for (int k = 0; k < nn; k++) {
            int s = __shfl_sync(0xFFFFFFFFu, e.x, k);
            float c = __int_as_float(__shfl_sync(0xFFFFFFFFu, e.y, k));
            uint2 u = ((const uint2*)(h + (size_t)s * CH))[lane];
            float2 f0 = __half22float2(*(__half2*)&u.x);
            float2 f1 = __half22float2(*(__half2*)&u.y);
            acc.x = fmaf(f0.x, c, acc.x);
            acc.y = fmaf(f0.y, c, acc.y);
            acc.z = fmaf(f1.x, c, acc.z);
            acc.w = fmaf(f1.y, c, acc.w);
        }
    }

    if (SPLIT) {
        __half2 h0 = __floats2half2_rn(fmaxf(acc.x, 0.f), fmaxf(acc.y, 0.f));
        __half2 h1 = __floats2half2_rn(fmaxf(acc.z, 0.f), fmaxf(acc.w, 0.f));
        uint2 pack;
        pack.x = *(unsigned*)&h0;
        pack.y = *(unsigned*)&h1;
        ((uint2*)(g_a2 + (size_t)node * CH))[lane] = pack;
    } else {
        ((float4*)(out + (size_t)node * CH))[lane] = acc;
    }
}

// ---------------------------------------------------------------------------
// Launch. Slot 4 (ncu-profiled) = gemm layer 1.
// ---------------------------------------------------------------------------
extern "C" void kernel_launch(void* const* d_in, const int* in_sizes, int n_in,
                              void* d_out, int out_size) {
    const float* x  = (const float*)d_in[0];
    const void*  ei = d_in[1];
    const float* W1 = (const float*)d_in[2];
    const float* b1 = (const float*)d_in[3];
    const float* W2 = (const float*)d_in[4];
    const float* b2 = (const float*)d_in[5];
    float*       out = (float*)d_out;

    const int N = in_sizes[0] / CH;
    const int E = in_sizes[1] / 2;
    const int ntiles = (N + 127) / 128;

    __half *hp = nullptr, *h2p = nullptr;
    cudaGetSymbolAddress((void**)&hp, g_h);
    cudaGetSymbolAddress((void**)&h2p, g_h2);

    cudaFuncSetAttribute(gemm_f16_kernel<1>,
                         cudaFuncAttributeMaxDynamicSharedMemorySize, SMEM_L1);
    cudaFuncSetAttribute(gemm_f16_kernel<2>,
                         cudaFuncAttributeMaxDynamicSharedMemorySize, SMEM_L2);

    const int T = 256;
    const int edge_grid = (E + T - 1) / T;
    const int node_grid = (N + T - 1) / T;
    const int conv_grid = (2 * E + T - 1) / T;
    const int warp_grid = (N * 32 + T - 1) / T;

    init_detect_kernel<<<node_grid, T>>>((const unsigned int*)ei, 2 * E, N); // 1
    convert_kernel<<<conv_grid, T>>>(ei, E);                                 // 2
    split_w_kernel<<<2, T>>>(W1, W2);                                        // 3
    gemm_f16_kernel<1><<<PGRID, 512, SMEM_L1>>>(x, hp, N, ntiles);           // 4 (profiled)
    dinv_alloc_kernel<<<node_grid, T>>>(N);                                  // 5
    csr_fill_kernel<<<edge_grid, T>>>(E);                                    // 6
    gather_kernel<true><<<warp_grid, T>>>(hp, b1, nullptr, N);               // 7
    gemm_f16_kernel<2><<<PGRID, 512, SMEM_L2>>>(nullptr, h2p, N, ntiles);    // 8
    gather_kernel<false><<<warp_grid, T>>>(h2p, b2, out, N);                 // 9
}